// round 11
// baseline (speedup 1.0000x reference)
#include <cuda_runtime.h>
#include <math.h>

#define BATCH 4
#define CCH   512
#define HW    4096
#define NTOK  4096
#define NGROUPS 32
#define CPG   16
#define GSIZE (CPG * HW)
#define SCALE_QK 0.044194173824159216f
#define SEG   24

// ---------------- scratch (packed bf16x2 stored as unsigned) ----------------
__device__ unsigned g_t32[BATCH * NTOK * CCH / 2];
__device__ unsigned g_q32[BATCH * NTOK * CCH / 2];
__device__ unsigned g_k32[BATCH * NTOK * CCH / 2];
__device__ unsigned g_v32[BATCH * NTOK * CCH / 2];
__device__ unsigned g_vt32[BATCH * NTOK * CCH / 2];
__device__ unsigned g_o32[BATCH * NTOK * CCH / 2];
__device__ unsigned g_w32[4 * CCH * CCH / 2];
__device__ float    g_y[BATCH * NTOK * CCH];
__device__ float    g_s[(size_t)BATCH * NTOK * NTOK];
__device__ unsigned g_p32[(size_t)BATCH * NTOK * NTOK / 2];
__device__ float    g_stats[BATCH * NGROUPS * 2];

// ---------------- helpers ----------------
__device__ __forceinline__ unsigned pack2(float lo, float hi) {
    unsigned r;
    asm("cvt.rn.bf16x2.f32 %0, %1, %2;" : "=r"(r) : "f"(hi), "f"(lo));
    return r;
}
__device__ __forceinline__ void mma16816(float* c, const unsigned* a, const unsigned* b) {
    asm volatile(
        "mma.sync.aligned.m16n8k16.row.col.f32.bf16.bf16.f32 "
        "{%0,%1,%2,%3}, {%4,%5,%6,%7}, {%8,%9}, {%0,%1,%2,%3};"
        : "+f"(c[0]), "+f"(c[1]), "+f"(c[2]), "+f"(c[3])
        : "r"(a[0]), "r"(a[1]), "r"(a[2]), "r"(a[3]), "r"(b[0]), "r"(b[1]));
}

// ---------------- GroupNorm stats ----------------
__global__ void gn_stats_kernel(const float* __restrict__ x) {
    int bg = blockIdx.x;
    const float4* p = (const float4*)(x + (size_t)bg * GSIZE);
    float s = 0.f, sq = 0.f;
    for (int i = threadIdx.x; i < GSIZE / 4; i += blockDim.x) {
        float4 v = p[i];
        s  += v.x + v.y + v.z + v.w;
        sq += v.x * v.x + v.y * v.y + v.z * v.z + v.w * v.w;
    }
    __shared__ float rs[256];
    __shared__ float rq[256];
    rs[threadIdx.x] = s; rq[threadIdx.x] = sq;
    __syncthreads();
    for (int o = 128; o > 0; o >>= 1) {
        if (threadIdx.x < o) {
            rs[threadIdx.x] += rs[threadIdx.x + o];
            rq[threadIdx.x] += rq[threadIdx.x + o];
        }
        __syncthreads();
    }
    if (threadIdx.x == 0) {
        float mean = rs[0] / (float)GSIZE;
        float var  = rq[0] / (float)GSIZE - mean * mean;
        g_stats[bg * 2 + 0] = mean;
        g_stats[bg * 2 + 1] = rsqrtf(var + 1e-6f);
    }
}

// ---------------- normalize + affine + transpose -> packed bf16 token-major ----------------
__global__ void gn_apply_transpose_kernel(const float* __restrict__ x,
                                          const float* __restrict__ gamma,
                                          const float* __restrict__ beta) {
    __shared__ float tile[32][33];
    int b  = blockIdx.z;
    int c0 = blockIdx.y * 32;
    int s0 = blockIdx.x * 32;
    int tx = threadIdx.x, ty = threadIdx.y;
#pragma unroll
    for (int r = 0; r < 4; r++) {
        int c = c0 + ty + r * 8;
        int g = c / CPG;
        float mean = g_stats[(b * NGROUPS + g) * 2 + 0];
        float rstd = g_stats[(b * NGROUPS + g) * 2 + 1];
        float v = x[((size_t)b * CCH + c) * HW + s0 + tx];
        tile[ty + r * 8][tx] = (v - mean) * rstd * gamma[c] + beta[c];
    }
    __syncthreads();
    if (tx < 16) {
#pragma unroll
        for (int r = 0; r < 4; r++) {
            int sl = ty + r * 8;
            float lo = tile[2 * tx + 0][sl];
            float hi = tile[2 * tx + 1][sl];
            g_t32[((size_t)b * NTOK + s0 + sl) * (CCH / 2) + (c0 >> 1) + tx] = pack2(lo, hi);
        }
    }
}

// ---------------- fp32 -> packed bf16 weight convert ----------------
__global__ void conv_w_kernel(const float* __restrict__ w, unsigned* __restrict__ o) {
    int i = blockIdx.x * 256 + threadIdx.x;
    float4 v = ((const float4*)w)[i];
    o[2 * i + 0] = pack2(v.x, v.y);
    o[2 * i + 1] = pack2(v.z, v.w);
}

// ---------------- bf16 transpose: v[b][tok][c] -> vt[b][c][tok] ----------------
__global__ void transpose_v_kernel() {
    __shared__ unsigned short tile[32][33];
    const unsigned short* in = (const unsigned short*)g_v32;
    unsigned short* out = (unsigned short*)g_vt32;
    int b  = blockIdx.z;
    int t0 = blockIdx.x * 32;
    int c0 = blockIdx.y * 32;
    int tx = threadIdx.x, ty = threadIdx.y;
#pragma unroll
    for (int r = 0; r < 4; r++) {
        int tk = t0 + ty + r * 8;
        tile[ty + r * 8][tx] = in[((size_t)b * NTOK + tk) * CCH + c0 + tx];
    }
    __syncthreads();
#pragma unroll
    for (int r = 0; r < 4; r++) {
        int c = c0 + ty + r * 8;
        out[((size_t)b * CCH + c) * NTOK + t0 + tx] = tile[tx][ty + r * 8];
    }
}

// ---------------- packed-bf16 NT tensor-core GEMM ----------------
// C = alpha * A @ B^T + bias.
// A: [M][K2] packed uints (bf16 pairs along k). B: [N][K2] packed uints.
// Cb != 0 -> packed bf16 out (row length N/2 uints); else fp32 out to Cf.
// CTA 128x128, 128 threads, warp tile 64x64, BK = 32 elems = 16 uints.
// SEG=24 swizzle: conflict-free fragment LDS.64 (see R10 notes).
// occupancy 3 CTAs/SM (12 warps) for latency hiding; reg budget 170 fits ~164 use.
__global__ void __launch_bounds__(128, 3)
hg_nt(const unsigned* __restrict__ A, const unsigned* __restrict__ B,
      unsigned* __restrict__ Cb, float* __restrict__ Cf,
      const float* __restrict__ bias,
      int N, int K2, float alpha, size_t sA, size_t sB, size_t sC) {
    A += (size_t)blockIdx.z * sA;
    B += (size_t)blockIdx.z * sB;

    __shared__ __align__(16) unsigned As[2][128 * SEG];
    __shared__ __align__(16) unsigned Bs[2][128 * SEG];

    const int tid  = threadIdx.x;
    const int lane = tid & 31;
    const int wid  = tid >> 5;
    const int wm   = (wid & 1) * 64;
    const int wn   = (wid >> 1) * 64;
    const int bm   = blockIdx.y * 128;
    const int bn   = blockIdx.x * 128;

    const unsigned* Ag = A + (size_t)(bm + tid) * K2;
    const unsigned* Bg = B + (size_t)(bn + tid) * K2;

    const int g = lane >> 2;
    const int t = lane & 3;
    const int col0 = 2 * t;
    const int col1 = 8 + 2 * t;

    float acc[4][8][4];
#pragma unroll
    for (int i = 0; i < 4; i++)
#pragma unroll
        for (int j = 0; j < 8; j++)
#pragma unroll
            for (int u = 0; u < 4; u++) acc[i][j][u] = 0.f;

    const int nchunk = K2 / 16;
    uint4 ra[4], rb[4];

    // ---- prologue: load + store chunk 0 ----
#pragma unroll
    for (int u = 0; u < 4; u++) ra[u] = *(const uint4*)(Ag + 4 * u);
#pragma unroll
    for (int u = 0; u < 4; u++) rb[u] = *(const uint4*)(Bg + 4 * u);
    {
        unsigned* d = &As[0][tid * SEG];
        *(uint4*)(d + 0)  = make_uint4(ra[0].x, ra[1].x, ra[0].y, ra[1].y);
        *(uint4*)(d + 4)  = make_uint4(ra[0].z, ra[1].z, ra[0].w, ra[1].w);
        *(uint4*)(d + 8)  = make_uint4(ra[2].x, ra[3].x, ra[2].y, ra[3].y);
        *(uint4*)(d + 12) = make_uint4(ra[2].z, ra[3].z, ra[2].w, ra[3].w);
        unsigned* e = &Bs[0][tid * SEG];
        *(uint4*)(e + 0)  = make_uint4(rb[0].x, rb[1].x, rb[0].y, rb[1].y);
        *(uint4*)(e + 4)  = make_uint4(rb[0].z, rb[1].z, rb[0].w, rb[1].w);
        *(uint4*)(e + 8)  = make_uint4(rb[2].x, rb[3].x, rb[2].y, rb[3].y);
        *(uint4*)(e + 12) = make_uint4(rb[2].z, rb[3].z, rb[2].w, rb[3].w);
    }
    __syncthreads();

    for (int ch = 0; ch < nchunk; ch++) {
        const int st = ch & 1;
        if (ch + 1 < nchunk) {
            const int kc = (ch + 1) * 16;
#pragma unroll
            for (int u = 0; u < 4; u++) ra[u] = *(const uint4*)(Ag + kc + 4 * u);
#pragma unroll
            for (int u = 0; u < 4; u++) rb[u] = *(const uint4*)(Bg + kc + 4 * u);
        }

#pragma unroll
        for (int kk = 0; kk < 2; kk++) {
            const int cc = (kk == 0) ? col0 : col1;
            unsigned af[4][4];
#pragma unroll
            for (int mi = 0; mi < 4; mi++) {
                int r0 = wm + mi * 16 + g;
                uint2 u0 = *(const uint2*)&As[st][r0 * SEG + cc];
                uint2 u1 = *(const uint2*)&As[st][(r0 + 8) * SEG + cc];
                af[mi][0] = u0.x; af[mi][1] = u1.x;
                af[mi][2] = u0.y; af[mi][3] = u1.y;
            }
            unsigned bfr[8][2];
#pragma unroll
            for (int nj = 0; nj < 8; nj++) {
                int rb0 = wn + nj * 8 + g;
                uint2 ub = *(const uint2*)&Bs[st][rb0 * SEG + cc];
                bfr[nj][0] = ub.x; bfr[nj][1] = ub.y;
            }
#pragma unroll
            for (int mi = 0; mi < 4; mi++)
#pragma unroll
                for (int nj = 0; nj < 8; nj++)
                    mma16816(acc[mi][nj], af[mi], bfr[nj]);
        }

        if (ch + 1 < nchunk) {
            unsigned* d = &As[st ^ 1][tid * SEG];
            *(uint4*)(d + 0)  = make_uint4(ra[0].x, ra[1].x, ra[0].y, ra[1].y);
            *(uint4*)(d + 4)  = make_uint4(ra[0].z, ra[1].z, ra[0].w, ra[1].w);
            *(uint4*)(d + 8)  = make_uint4(ra[2].x, ra[3].x, ra[2].y, ra[3].y);
            *(uint4*)(d + 12) = make_uint4(ra[2].z, ra[3].z, ra[2].w, ra[3].w);
            unsigned* e = &Bs[st ^ 1][tid * SEG];
            *(uint4*)(e + 0)  = make_uint4(rb[0].x, rb[1].x, rb[0].y, rb[1].y);
            *(uint4*)(e + 4)  = make_uint4(rb[0].z, rb[1].z, rb[0].w, rb[1].w);
            *(uint4*)(e + 8)  = make_uint4(rb[2].x, rb[3].x, rb[2].y, rb[3].y);
            *(uint4*)(e + 12) = make_uint4(rb[2].z, rb[3].z, rb[2].w, rb[3].w);
        }
        __syncthreads();
    }

    // ---- epilogue ----
    const int lr  = g;
    const int lc2 = t * 2;
#pragma unroll
    for (int mi = 0; mi < 4; mi++) {
        int row0 = bm + wm + mi * 16 + lr;
#pragma unroll
        for (int nj = 0; nj < 8; nj++) {
            int col = bn + wn + nj * 8 + lc2;
            float b0 = 0.f, b1 = 0.f;
            if (bias) { b0 = bias[col]; b1 = bias[col + 1]; }
            float v0 = acc[mi][nj][0] * alpha + b0;
            float v1 = acc[mi][nj][1] * alpha + b1;
            float v2 = acc[mi][nj][2] * alpha + b0;
            float v3 = acc[mi][nj][3] * alpha + b1;
            if (Cb) {
                unsigned* C = Cb + blockIdx.z * sC;
                int n2 = N >> 1;
                C[(size_t)row0 * n2 + (col >> 1)]       = pack2(v0, v1);
                C[(size_t)(row0 + 8) * n2 + (col >> 1)] = pack2(v2, v3);
            } else {
                float* C = Cf + blockIdx.z * sC;
                *(float2*)(C + (size_t)row0 * N + col)       = make_float2(v0, v1);
                *(float2*)(C + (size_t)(row0 + 8) * N + col) = make_float2(v2, v3);
            }
        }
    }
}

// ---------------- row softmax: fp32 scores -> packed bf16 probs ----------------
__global__ void softmax_rows_kernel() {
    size_t row = blockIdx.x;
    const float4* pin = (const float4*)(g_s + row * (size_t)NTOK);
    uint2* pout = (uint2*)(g_p32 + row * (size_t)(NTOK / 2));
    int t = threadIdx.x;
    float v[16];
    float lmax = -1e30f;
#pragma unroll
    for (int i = 0; i < 4; i++) {
        float4 u = pin[t + i * 256];
        v[i * 4 + 0] = u.x; v[i * 4 + 1] = u.y;
        v[i * 4 + 2] = u.z; v[i * 4 + 3] = u.w;
        lmax = fmaxf(fmaxf(fmaxf(u.x, u.y), fmaxf(u.z, u.w)), lmax);
    }
    __shared__ float red[256];
    red[t] = lmax;
    __syncthreads();
    for (int o = 128; o > 0; o >>= 1) {
        if (t < o) red[t] = fmaxf(red[t], red[t + o]);
        __syncthreads();
    }
    float m = red[0];
    __syncthreads();
    float lsum = 0.f;
#pragma unroll
    for (int i = 0; i < 16; i++) {
        v[i] = __expf(v[i] - m);
        lsum += v[i];
    }
    red[t] = lsum;
    __syncthreads();
    for (int o = 128; o > 0; o >>= 1) {
        if (t < o) red[t] += red[t + o];
        __syncthreads();
    }
    float inv = 1.f / red[0];
#pragma unroll
    for (int i = 0; i < 4; i++) {
        int idx = t + i * 256;
        uint2 w;
        w.x = pack2(v[i * 4 + 0] * inv, v[i * 4 + 1] * inv);
        w.y = pack2(v[i * 4 + 2] * inv, v[i * 4 + 3] * inv);
        pout[idx] = w;
    }
}

// ---------------- y[b,s,c] -> out[b,c,s] + residual ----------------
__global__ void add_residual_transpose_kernel(const float* __restrict__ x,
                                              float* __restrict__ out) {
    __shared__ float tile[32][33];
    int b  = blockIdx.z;
    int c0 = blockIdx.y * 32;
    int s0 = blockIdx.x * 32;
    int tx = threadIdx.x, ty = threadIdx.y;
#pragma unroll
    for (int r = 0; r < 4; r++) {
        int s = s0 + ty + r * 8;
        tile[ty + r * 8][tx] = g_y[((size_t)b * NTOK + s) * CCH + c0 + tx];
    }
    __syncthreads();
#pragma unroll
    for (int r = 0; r < 4; r++) {
        int c = c0 + ty + r * 8;
        size_t idx = ((size_t)b * CCH + c) * HW + s0 + tx;
        out[idx] = tile[tx][ty + r * 8] + x[idx];
    }
}

// ---------------- launch ----------------
extern "C" void kernel_launch(void* const* d_in, const int* in_sizes, int n_in,
                              void* d_out, int out_size) {
    const float* x     = (const float*)d_in[0];
    const float* gamma = (const float*)d_in[1];
    const float* beta  = (const float*)d_in[2];
    const float* wq_w  = (const float*)d_in[3];
    const float* wq_b  = (const float*)d_in[4];
    const float* wk_w  = (const float*)d_in[5];
    const float* wk_b  = (const float*)d_in[6];
    const float* wv_w  = (const float*)d_in[7];
    const float* wv_b  = (const float*)d_in[8];
    const float* out_w = (const float*)d_in[9];
    const float* out_b = (const float*)d_in[10];
    float* out = (float*)d_out;

    unsigned *tbuf, *qbuf, *kbuf, *vbuf, *vtbuf, *obuf, *wbuf, *pbuf;
    float *sbuf, *ybuf;
    cudaGetSymbolAddress((void**)&tbuf,  g_t32);
    cudaGetSymbolAddress((void**)&qbuf,  g_q32);
    cudaGetSymbolAddress((void**)&kbuf,  g_k32);
    cudaGetSymbolAddress((void**)&vbuf,  g_v32);
    cudaGetSymbolAddress((void**)&vtbuf, g_vt32);
    cudaGetSymbolAddress((void**)&obuf,  g_o32);
    cudaGetSymbolAddress((void**)&wbuf,  g_w32);
    cudaGetSymbolAddress((void**)&pbuf,  g_p32);
    cudaGetSymbolAddress((void**)&sbuf,  g_s);
    cudaGetSymbolAddress((void**)&ybuf,  g_y);

    const int WU = CCH * CCH / 2;                  // uints per weight matrix
    const int MT = BATCH * NTOK;                   // 16384 rows
    const int K2C = CCH / 2;                       // 256 uints
    const int K2T = NTOK / 2;                      // 2048 uints
    dim3 tthr(32, 8);

    gn_stats_kernel<<<BATCH * NGROUPS, 256>>>(x);
    gn_apply_transpose_kernel<<<dim3(HW / 32, CCH / 32, BATCH), tthr>>>(x, gamma, beta);
    conv_w_kernel<<<CCH * CCH / 1024, 256>>>(wq_w, wbuf + 0 * WU);
    conv_w_kernel<<<CCH * CCH / 1024, 256>>>(wk_w, wbuf + 1 * WU);
    conv_w_kernel<<<CCH * CCH / 1024, 256>>>(wv_w, wbuf + 2 * WU);
    conv_w_kernel<<<CCH * CCH / 1024, 256>>>(out_w, wbuf + 3 * WU);

    // Q/K/V projections (NT, bias fused, packed-bf16 out)
    hg_nt<<<dim3(CCH / 128, MT / 128, 1), 128>>>(
        tbuf, wbuf + 0 * WU, qbuf, 0, wq_b, CCH, K2C, 1.f, 0, 0, 0);
    hg_nt<<<dim3(CCH / 128, MT / 128, 1), 128>>>(
        tbuf, wbuf + 1 * WU, kbuf, 0, wk_b, CCH, K2C, 1.f, 0, 0, 0);
    hg_nt<<<dim3(CCH / 128, MT / 128, 1), 128>>>(
        tbuf, wbuf + 2 * WU, vbuf, 0, wv_b, CCH, K2C, 1.f, 0, 0, 0);

    // V transpose: v[b][tok][c] -> vt[b][c][tok]
    transpose_v_kernel<<<dim3(NTOK / 32, CCH / 32, BATCH), tthr>>>();

    // scores = Q @ K^T * scale (batched NT, fp32 out)
    hg_nt<<<dim3(NTOK / 128, NTOK / 128, BATCH), 128>>>(
        qbuf, kbuf, 0, sbuf, 0, NTOK, K2C, SCALE_QK,
        (size_t)NTOK * K2C, (size_t)NTOK * K2C, (size_t)NTOK * NTOK);

    softmax_rows_kernel<<<BATCH * NTOK, 256>>>();

    // O = P @ V = P @ (VT)^T (batched NT, packed-bf16 out)
    hg_nt<<<dim3(CCH / 128, NTOK / 128, BATCH), 128>>>(
        pbuf, vtbuf, obuf, 0, 0, CCH, K2T, 1.f,
        (size_t)NTOK * K2T, (size_t)CCH * K2T, (size_t)NTOK * K2C);

    // out projection (NT, bias fused, fp32 out)
    hg_nt<<<dim3(CCH / 128, MT / 128, 1), 128>>>(
        obuf, wbuf + 3 * WU, 0, ybuf, out_b, CCH, K2C, 1.f, 0, 0, 0);

    add_residual_transpose_kernel<<<dim3(HW / 32, CCH / 32, BATCH), tthr>>>(x, out);
}

// round 12
// speedup vs baseline: 2.6516x; 2.6516x over previous
#include <cuda_runtime.h>
#include <math.h>

#define BATCH 4
#define CCH   512
#define HW    4096
#define NTOK  4096
#define NGROUPS 32
#define CPG   16
#define GSIZE (CPG * HW)
#define SCALE_QK 0.044194173824159216f
#define SEG   24

// ---------------- scratch (packed bf16x2 stored as unsigned) ----------------
__device__ unsigned g_t32[BATCH * NTOK * CCH / 2];
__device__ unsigned g_q32[BATCH * NTOK * CCH / 2];
__device__ unsigned g_k32[BATCH * NTOK * CCH / 2];
__device__ unsigned g_v32[BATCH * NTOK * CCH / 2];
__device__ unsigned g_vt32[BATCH * NTOK * CCH / 2];
__device__ unsigned g_o32[BATCH * NTOK * CCH / 2];
__device__ unsigned g_w32[4 * CCH * CCH / 2];
__device__ float    g_y[BATCH * NTOK * CCH];
__device__ float    g_s[(size_t)BATCH * NTOK * NTOK];
__device__ unsigned g_p32[(size_t)BATCH * NTOK * NTOK / 2];
__device__ float    g_stats[BATCH * NGROUPS * 2];

// ---------------- helpers ----------------
__device__ __forceinline__ unsigned pack2(float lo, float hi) {
    unsigned r;
    asm("cvt.rn.bf16x2.f32 %0, %1, %2;" : "=r"(r) : "f"(hi), "f"(lo));
    return r;
}
__device__ __forceinline__ void mma16816(float* c, const unsigned* a, const unsigned* b) {
    asm volatile(
        "mma.sync.aligned.m16n8k16.row.col.f32.bf16.bf16.f32 "
        "{%0,%1,%2,%3}, {%4,%5,%6,%7}, {%8,%9}, {%0,%1,%2,%3};"
        : "+f"(c[0]), "+f"(c[1]), "+f"(c[2]), "+f"(c[3])
        : "r"(a[0]), "r"(a[1]), "r"(a[2]), "r"(a[3]), "r"(b[0]), "r"(b[1]));
}

// ---------------- GroupNorm stats ----------------
__global__ void gn_stats_kernel(const float* __restrict__ x) {
    int bg = blockIdx.x;
    const float4* p = (const float4*)(x + (size_t)bg * GSIZE);
    float s = 0.f, sq = 0.f;
    for (int i = threadIdx.x; i < GSIZE / 4; i += blockDim.x) {
        float4 v = p[i];
        s  += v.x + v.y + v.z + v.w;
        sq += v.x * v.x + v.y * v.y + v.z * v.z + v.w * v.w;
    }
    __shared__ float rs[256];
    __shared__ float rq[256];
    rs[threadIdx.x] = s; rq[threadIdx.x] = sq;
    __syncthreads();
    for (int o = 128; o > 0; o >>= 1) {
        if (threadIdx.x < o) {
            rs[threadIdx.x] += rs[threadIdx.x + o];
            rq[threadIdx.x] += rq[threadIdx.x + o];
        }
        __syncthreads();
    }
    if (threadIdx.x == 0) {
        float mean = rs[0] / (float)GSIZE;
        float var  = rq[0] / (float)GSIZE - mean * mean;
        g_stats[bg * 2 + 0] = mean;
        g_stats[bg * 2 + 1] = rsqrtf(var + 1e-6f);
    }
}

// ---------------- normalize + affine + transpose -> packed bf16 token-major ----------------
__global__ void gn_apply_transpose_kernel(const float* __restrict__ x,
                                          const float* __restrict__ gamma,
                                          const float* __restrict__ beta) {
    __shared__ float tile[32][33];
    int b  = blockIdx.z;
    int c0 = blockIdx.y * 32;
    int s0 = blockIdx.x * 32;
    int tx = threadIdx.x, ty = threadIdx.y;
#pragma unroll
    for (int r = 0; r < 4; r++) {
        int c = c0 + ty + r * 8;
        int g = c / CPG;
        float mean = g_stats[(b * NGROUPS + g) * 2 + 0];
        float rstd = g_stats[(b * NGROUPS + g) * 2 + 1];
        float v = x[((size_t)b * CCH + c) * HW + s0 + tx];
        tile[ty + r * 8][tx] = (v - mean) * rstd * gamma[c] + beta[c];
    }
    __syncthreads();
    if (tx < 16) {
#pragma unroll
        for (int r = 0; r < 4; r++) {
            int sl = ty + r * 8;
            float lo = tile[2 * tx + 0][sl];
            float hi = tile[2 * tx + 1][sl];
            g_t32[((size_t)b * NTOK + s0 + sl) * (CCH / 2) + (c0 >> 1) + tx] = pack2(lo, hi);
        }
    }
}

// ---------------- fp32 -> packed bf16 weight convert ----------------
__global__ void conv_w_kernel(const float* __restrict__ w, unsigned* __restrict__ o) {
    int i = blockIdx.x * 256 + threadIdx.x;
    float4 v = ((const float4*)w)[i];
    o[2 * i + 0] = pack2(v.x, v.y);
    o[2 * i + 1] = pack2(v.z, v.w);
}

// ---------------- bf16 transpose: v[b][tok][c] -> vt[b][c][tok] ----------------
__global__ void transpose_v_kernel() {
    __shared__ unsigned short tile[32][33];
    const unsigned short* in = (const unsigned short*)g_v32;
    unsigned short* out = (unsigned short*)g_vt32;
    int b  = blockIdx.z;
    int t0 = blockIdx.x * 32;
    int c0 = blockIdx.y * 32;
    int tx = threadIdx.x, ty = threadIdx.y;
#pragma unroll
    for (int r = 0; r < 4; r++) {
        int tk = t0 + ty + r * 8;
        tile[ty + r * 8][tx] = in[((size_t)b * NTOK + tk) * CCH + c0 + tx];
    }
    __syncthreads();
#pragma unroll
    for (int r = 0; r < 4; r++) {
        int c = c0 + ty + r * 8;
        out[((size_t)b * CCH + c) * NTOK + t0 + tx] = tile[tx][ty + r * 8];
    }
}

// ---------------- packed-bf16 NT tensor-core GEMM ----------------
// C = alpha * A @ B^T + bias.
// A: [M][K2] packed uints (bf16 pairs along k). B: [N][K2] packed uints.
// Cb != 0 -> packed bf16 out (row length N/2 uints); else fp32 out to Cf.
// CTA 128x128, 256 threads (8 warps), warp tile 64x32, BK = 32 elems = 16 uints.
// SEG=24 swizzle: conflict-free fragment LDS.64.
// 2 CTAs/SM = 16 warps/SM (~110 regs/thread, no spill under 128-reg cap).
__global__ void __launch_bounds__(256, 2)
hg_nt(const unsigned* __restrict__ A, const unsigned* __restrict__ B,
      unsigned* __restrict__ Cb, float* __restrict__ Cf,
      const float* __restrict__ bias,
      int N, int K2, float alpha, size_t sA, size_t sB, size_t sC) {
    A += (size_t)blockIdx.z * sA;
    B += (size_t)blockIdx.z * sB;

    __shared__ __align__(16) unsigned As[2][128 * SEG];
    __shared__ __align__(16) unsigned Bs[2][128 * SEG];

    const int tid  = threadIdx.x;
    const int lane = tid & 31;
    const int wid  = tid >> 5;          // 0..7
    const int wm   = (wid & 1) * 64;
    const int wn   = (wid >> 1) * 32;
    const int bm   = blockIdx.y * 128;
    const int bn   = blockIdx.x * 128;

    const int lrow = tid >> 1;          // 0..127: tile row this thread loads
    const int lhalf = tid & 1;          // 0/1: which 8-uint half of the row
    const unsigned* Ag = A + (size_t)(bm + lrow) * K2 + lhalf * 8;
    const unsigned* Bg = B + (size_t)(bn + lrow) * K2 + lhalf * 8;
    const int soff = lrow * SEG + lhalf * 8;

    const int g = lane >> 2;
    const int t = lane & 3;
    const int col0 = 2 * t;
    const int col1 = 8 + 2 * t;

    float acc[4][4][4];
#pragma unroll
    for (int i = 0; i < 4; i++)
#pragma unroll
        for (int j = 0; j < 4; j++)
#pragma unroll
            for (int u = 0; u < 4; u++) acc[i][j][u] = 0.f;

    const int nchunk = K2 / 16;
    uint4 ga[2], gb[2];

    // ---- prologue: load + store chunk 0 ----
    ga[0] = *(const uint4*)(Ag + 0);
    ga[1] = *(const uint4*)(Ag + 4);
    gb[0] = *(const uint4*)(Bg + 0);
    gb[1] = *(const uint4*)(Bg + 4);
    {
        unsigned* d = &As[0][soff];
        *(uint4*)(d + 0) = make_uint4(ga[0].x, ga[1].x, ga[0].y, ga[1].y);
        *(uint4*)(d + 4) = make_uint4(ga[0].z, ga[1].z, ga[0].w, ga[1].w);
        unsigned* e = &Bs[0][soff];
        *(uint4*)(e + 0) = make_uint4(gb[0].x, gb[1].x, gb[0].y, gb[1].y);
        *(uint4*)(e + 4) = make_uint4(gb[0].z, gb[1].z, gb[0].w, gb[1].w);
    }
    __syncthreads();

    for (int ch = 0; ch < nchunk; ch++) {
        const int st = ch & 1;
        if (ch + 1 < nchunk) {
            const int kc = (ch + 1) * 16;
            ga[0] = *(const uint4*)(Ag + kc + 0);
            ga[1] = *(const uint4*)(Ag + kc + 4);
            gb[0] = *(const uint4*)(Bg + kc + 0);
            gb[1] = *(const uint4*)(Bg + kc + 4);
        }

#pragma unroll
        for (int kk = 0; kk < 2; kk++) {
            const int cc = (kk == 0) ? col0 : col1;
            unsigned af[4][4];
#pragma unroll
            for (int mi = 0; mi < 4; mi++) {
                int r0 = wm + mi * 16 + g;
                uint2 u0 = *(const uint2*)&As[st][r0 * SEG + cc];
                uint2 u1 = *(const uint2*)&As[st][(r0 + 8) * SEG + cc];
                af[mi][0] = u0.x; af[mi][1] = u1.x;
                af[mi][2] = u0.y; af[mi][3] = u1.y;
            }
            unsigned bfr[4][2];
#pragma unroll
            for (int nj = 0; nj < 4; nj++) {
                int rb0 = wn + nj * 8 + g;
                uint2 ub = *(const uint2*)&Bs[st][rb0 * SEG + cc];
                bfr[nj][0] = ub.x; bfr[nj][1] = ub.y;
            }
#pragma unroll
            for (int mi = 0; mi < 4; mi++)
#pragma unroll
                for (int nj = 0; nj < 4; nj++)
                    mma16816(acc[mi][nj], af[mi], bfr[nj]);
        }

        if (ch + 1 < nchunk) {
            unsigned* d = &As[st ^ 1][soff];
            *(uint4*)(d + 0) = make_uint4(ga[0].x, ga[1].x, ga[0].y, ga[1].y);
            *(uint4*)(d + 4) = make_uint4(ga[0].z, ga[1].z, ga[0].w, ga[1].w);
            unsigned* e = &Bs[st ^ 1][soff];
            *(uint4*)(e + 0) = make_uint4(gb[0].x, gb[1].x, gb[0].y, gb[1].y);
            *(uint4*)(e + 4) = make_uint4(gb[0].z, gb[1].z, gb[0].w, gb[1].w);
        }
        __syncthreads();
    }

    // ---- epilogue ----
    const int lr  = g;
    const int lc2 = t * 2;
#pragma unroll
    for (int mi = 0; mi < 4; mi++) {
        int row0 = bm + wm + mi * 16 + lr;
#pragma unroll
        for (int nj = 0; nj < 4; nj++) {
            int col = bn + wn + nj * 8 + lc2;
            float b0 = 0.f, b1 = 0.f;
            if (bias) { b0 = bias[col]; b1 = bias[col + 1]; }
            float v0 = acc[mi][nj][0] * alpha + b0;
            float v1 = acc[mi][nj][1] * alpha + b1;
            float v2 = acc[mi][nj][2] * alpha + b0;
            float v3 = acc[mi][nj][3] * alpha + b1;
            if (Cb) {
                unsigned* C = Cb + blockIdx.z * sC;
                int n2 = N >> 1;
                C[(size_t)row0 * n2 + (col >> 1)]       = pack2(v0, v1);
                C[(size_t)(row0 + 8) * n2 + (col >> 1)] = pack2(v2, v3);
            } else {
                float* C = Cf + blockIdx.z * sC;
                *(float2*)(C + (size_t)row0 * N + col)       = make_float2(v0, v1);
                *(float2*)(C + (size_t)(row0 + 8) * N + col) = make_float2(v2, v3);
            }
        }
    }
}

// ---------------- row softmax: fp32 scores -> packed bf16 probs ----------------
__global__ void softmax_rows_kernel() {
    size_t row = blockIdx.x;
    const float4* pin = (const float4*)(g_s + row * (size_t)NTOK);
    uint2* pout = (uint2*)(g_p32 + row * (size_t)(NTOK / 2));
    int t = threadIdx.x;
    float v[16];
    float lmax = -1e30f;
#pragma unroll
    for (int i = 0; i < 4; i++) {
        float4 u = pin[t + i * 256];
        v[i * 4 + 0] = u.x; v[i * 4 + 1] = u.y;
        v[i * 4 + 2] = u.z; v[i * 4 + 3] = u.w;
        lmax = fmaxf(fmaxf(fmaxf(u.x, u.y), fmaxf(u.z, u.w)), lmax);
    }
    __shared__ float red[256];
    red[t] = lmax;
    __syncthreads();
    for (int o = 128; o > 0; o >>= 1) {
        if (t < o) red[t] = fmaxf(red[t], red[t + o]);
        __syncthreads();
    }
    float m = red[0];
    __syncthreads();
    float lsum = 0.f;
#pragma unroll
    for (int i = 0; i < 16; i++) {
        v[i] = __expf(v[i] - m);
        lsum += v[i];
    }
    red[t] = lsum;
    __syncthreads();
    for (int o = 128; o > 0; o >>= 1) {
        if (t < o) red[t] += red[t + o];
        __syncthreads();
    }
    float inv = 1.f / red[0];
#pragma unroll
    for (int i = 0; i < 4; i++) {
        int idx = t + i * 256;
        uint2 w;
        w.x = pack2(v[i * 4 + 0] * inv, v[i * 4 + 1] * inv);
        w.y = pack2(v[i * 4 + 2] * inv, v[i * 4 + 3] * inv);
        pout[idx] = w;
    }
}

// ---------------- y[b,s,c] -> out[b,c,s] + residual ----------------
__global__ void add_residual_transpose_kernel(const float* __restrict__ x,
                                              float* __restrict__ out) {
    __shared__ float tile[32][33];
    int b  = blockIdx.z;
    int c0 = blockIdx.y * 32;
    int s0 = blockIdx.x * 32;
    int tx = threadIdx.x, ty = threadIdx.y;
#pragma unroll
    for (int r = 0; r < 4; r++) {
        int s = s0 + ty + r * 8;
        tile[ty + r * 8][tx] = g_y[((size_t)b * NTOK + s) * CCH + c0 + tx];
    }
    __syncthreads();
#pragma unroll
    for (int r = 0; r < 4; r++) {
        int c = c0 + ty + r * 8;
        size_t idx = ((size_t)b * CCH + c) * HW + s0 + tx;
        out[idx] = tile[tx][ty + r * 8] + x[idx];
    }
}

// ---------------- launch ----------------
extern "C" void kernel_launch(void* const* d_in, const int* in_sizes, int n_in,
                              void* d_out, int out_size) {
    const float* x     = (const float*)d_in[0];
    const float* gamma = (const float*)d_in[1];
    const float* beta  = (const float*)d_in[2];
    const float* wq_w  = (const float*)d_in[3];
    const float* wq_b  = (const float*)d_in[4];
    const float* wk_w  = (const float*)d_in[5];
    const float* wk_b  = (const float*)d_in[6];
    const float* wv_w  = (const float*)d_in[7];
    const float* wv_b  = (const float*)d_in[8];
    const float* out_w = (const float*)d_in[9];
    const float* out_b = (const float*)d_in[10];
    float* out = (float*)d_out;

    unsigned *tbuf, *qbuf, *kbuf, *vbuf, *vtbuf, *obuf, *wbuf, *pbuf;
    float *sbuf, *ybuf;
    cudaGetSymbolAddress((void**)&tbuf,  g_t32);
    cudaGetSymbolAddress((void**)&qbuf,  g_q32);
    cudaGetSymbolAddress((void**)&kbuf,  g_k32);
    cudaGetSymbolAddress((void**)&vbuf,  g_v32);
    cudaGetSymbolAddress((void**)&vtbuf, g_vt32);
    cudaGetSymbolAddress((void**)&obuf,  g_o32);
    cudaGetSymbolAddress((void**)&wbuf,  g_w32);
    cudaGetSymbolAddress((void**)&pbuf,  g_p32);
    cudaGetSymbolAddress((void**)&sbuf,  g_s);
    cudaGetSymbolAddress((void**)&ybuf,  g_y);

    const int WU = CCH * CCH / 2;                  // uints per weight matrix
    const int MT = BATCH * NTOK;                   // 16384 rows
    const int K2C = CCH / 2;                       // 256 uints
    const int K2T = NTOK / 2;                      // 2048 uints
    dim3 tthr(32, 8);

    gn_stats_kernel<<<BATCH * NGROUPS, 256>>>(x);
    gn_apply_transpose_kernel<<<dim3(HW / 32, CCH / 32, BATCH), tthr>>>(x, gamma, beta);
    conv_w_kernel<<<CCH * CCH / 1024, 256>>>(wq_w, wbuf + 0 * WU);
    conv_w_kernel<<<CCH * CCH / 1024, 256>>>(wk_w, wbuf + 1 * WU);
    conv_w_kernel<<<CCH * CCH / 1024, 256>>>(wv_w, wbuf + 2 * WU);
    conv_w_kernel<<<CCH * CCH / 1024, 256>>>(out_w, wbuf + 3 * WU);

    // Q/K/V projections (NT, bias fused, packed-bf16 out)
    hg_nt<<<dim3(CCH / 128, MT / 128, 1), 256>>>(
        tbuf, wbuf + 0 * WU, qbuf, 0, wq_b, CCH, K2C, 1.f, 0, 0, 0);
    hg_nt<<<dim3(CCH / 128, MT / 128, 1), 256>>>(
        tbuf, wbuf + 1 * WU, kbuf, 0, wk_b, CCH, K2C, 1.f, 0, 0, 0);
    hg_nt<<<dim3(CCH / 128, MT / 128, 1), 256>>>(
        tbuf, wbuf + 2 * WU, vbuf, 0, wv_b, CCH, K2C, 1.f, 0, 0, 0);

    // V transpose: v[b][tok][c] -> vt[b][c][tok]
    transpose_v_kernel<<<dim3(NTOK / 32, CCH / 32, BATCH), tthr>>>();

    // scores = Q @ K^T * scale (batched NT, fp32 out)
    hg_nt<<<dim3(NTOK / 128, NTOK / 128, BATCH), 256>>>(
        qbuf, kbuf, 0, sbuf, 0, NTOK, K2C, SCALE_QK,
        (size_t)NTOK * K2C, (size_t)NTOK * K2C, (size_t)NTOK * NTOK);

    softmax_rows_kernel<<<BATCH * NTOK, 256>>>();

    // O = P @ V = P @ (VT)^T (batched NT, packed-bf16 out)
    hg_nt<<<dim3(CCH / 128, NTOK / 128, BATCH), 256>>>(
        pbuf, vtbuf, obuf, 0, 0, CCH, K2T, 1.f,
        (size_t)NTOK * K2T, (size_t)CCH * K2T, (size_t)NTOK * K2C);

    // out projection (NT, bias fused, fp32 out)
    hg_nt<<<dim3(CCH / 128, MT / 128, 1), 256>>>(
        obuf, wbuf + 3 * WU, 0, ybuf, out_b, CCH, K2C, 1.f, 0, 0, 0);

    add_residual_transpose_kernel<<<dim3(HW / 32, CCH / 32, BATCH), tthr>>>(x, out);
}

// round 13
// speedup vs baseline: 2.6871x; 1.0134x over previous
#include <cuda_runtime.h>
#include <math.h>

#define BATCH 4
#define CCH   512
#define HW    4096
#define NTOK  4096
#define NGROUPS 32
#define CPG   16
#define GSIZE (CPG * HW)
#define SCALE_QK 0.044194173824159216f
#define SEG   24

// ---------------- scratch (packed bf16x2 stored as unsigned) ----------------
__device__ unsigned g_t32[BATCH * NTOK * CCH / 2];
__device__ unsigned g_q32[BATCH * NTOK * CCH / 2];
__device__ unsigned g_k32[BATCH * NTOK * CCH / 2];
__device__ unsigned g_v32[BATCH * NTOK * CCH / 2];
__device__ unsigned g_vt32[BATCH * NTOK * CCH / 2];
__device__ unsigned g_o32[BATCH * NTOK * CCH / 2];
__device__ unsigned g_w32[4 * CCH * CCH / 2];
__device__ float    g_y[BATCH * NTOK * CCH];
__device__ unsigned g_s32[(size_t)BATCH * NTOK * NTOK / 2];   // bf16 scores -> probs (in place)
__device__ float    g_stats[BATCH * NGROUPS * 2];

// ---------------- helpers ----------------
__device__ __forceinline__ unsigned pack2(float lo, float hi) {
    unsigned r;
    asm("cvt.rn.bf16x2.f32 %0, %1, %2;" : "=r"(r) : "f"(hi), "f"(lo));
    return r;
}
__device__ __forceinline__ float blo(unsigned u) { return __uint_as_float(u << 16); }
__device__ __forceinline__ float bhi(unsigned u) { return __uint_as_float(u & 0xffff0000u); }
__device__ __forceinline__ void mma16816(float* c, const unsigned* a, const unsigned* b) {
    asm volatile(
        "mma.sync.aligned.m16n8k16.row.col.f32.bf16.bf16.f32 "
        "{%0,%1,%2,%3}, {%4,%5,%6,%7}, {%8,%9}, {%0,%1,%2,%3};"
        : "+f"(c[0]), "+f"(c[1]), "+f"(c[2]), "+f"(c[3])
        : "r"(a[0]), "r"(a[1]), "r"(a[2]), "r"(a[3]), "r"(b[0]), "r"(b[1]));
}

// ---------------- GroupNorm stats ----------------
__global__ void gn_stats_kernel(const float* __restrict__ x) {
    int bg = blockIdx.x;
    const float4* p = (const float4*)(x + (size_t)bg * GSIZE);
    float s = 0.f, sq = 0.f;
    for (int i = threadIdx.x; i < GSIZE / 4; i += blockDim.x) {
        float4 v = p[i];
        s  += v.x + v.y + v.z + v.w;
        sq += v.x * v.x + v.y * v.y + v.z * v.z + v.w * v.w;
    }
    __shared__ float rs[256];
    __shared__ float rq[256];
    rs[threadIdx.x] = s; rq[threadIdx.x] = sq;
    __syncthreads();
    for (int o = 128; o > 0; o >>= 1) {
        if (threadIdx.x < o) {
            rs[threadIdx.x] += rs[threadIdx.x + o];
            rq[threadIdx.x] += rq[threadIdx.x + o];
        }
        __syncthreads();
    }
    if (threadIdx.x == 0) {
        float mean = rs[0] / (float)GSIZE;
        float var  = rq[0] / (float)GSIZE - mean * mean;
        g_stats[bg * 2 + 0] = mean;
        g_stats[bg * 2 + 1] = rsqrtf(var + 1e-6f);
    }
}

// ---------------- normalize + affine + transpose -> packed bf16 token-major ----------------
__global__ void gn_apply_transpose_kernel(const float* __restrict__ x,
                                          const float* __restrict__ gamma,
                                          const float* __restrict__ beta) {
    __shared__ float tile[32][33];
    int b  = blockIdx.z;
    int c0 = blockIdx.y * 32;
    int s0 = blockIdx.x * 32;
    int tx = threadIdx.x, ty = threadIdx.y;
#pragma unroll
    for (int r = 0; r < 4; r++) {
        int c = c0 + ty + r * 8;
        int g = c / CPG;
        float mean = g_stats[(b * NGROUPS + g) * 2 + 0];
        float rstd = g_stats[(b * NGROUPS + g) * 2 + 1];
        float v = x[((size_t)b * CCH + c) * HW + s0 + tx];
        tile[ty + r * 8][tx] = (v - mean) * rstd * gamma[c] + beta[c];
    }
    __syncthreads();
    if (tx < 16) {
#pragma unroll
        for (int r = 0; r < 4; r++) {
            int sl = ty + r * 8;
            float lo = tile[2 * tx + 0][sl];
            float hi = tile[2 * tx + 1][sl];
            g_t32[((size_t)b * NTOK + s0 + sl) * (CCH / 2) + (c0 >> 1) + tx] = pack2(lo, hi);
        }
    }
}

// ---------------- fp32 -> packed bf16 weight convert ----------------
__global__ void conv_w_kernel(const float* __restrict__ w, unsigned* __restrict__ o) {
    int i = blockIdx.x * 256 + threadIdx.x;
    float4 v = ((const float4*)w)[i];
    o[2 * i + 0] = pack2(v.x, v.y);
    o[2 * i + 1] = pack2(v.z, v.w);
}

// ---------------- bf16 transpose: v[b][tok][c] -> vt[b][c][tok] ----------------
__global__ void transpose_v_kernel() {
    __shared__ unsigned short tile[32][33];
    const unsigned short* in = (const unsigned short*)g_v32;
    unsigned short* out = (unsigned short*)g_vt32;
    int b  = blockIdx.z;
    int t0 = blockIdx.x * 32;
    int c0 = blockIdx.y * 32;
    int tx = threadIdx.x, ty = threadIdx.y;
#pragma unroll
    for (int r = 0; r < 4; r++) {
        int tk = t0 + ty + r * 8;
        tile[ty + r * 8][tx] = in[((size_t)b * NTOK + tk) * CCH + c0 + tx];
    }
    __syncthreads();
#pragma unroll
    for (int r = 0; r < 4; r++) {
        int c = c0 + ty + r * 8;
        out[((size_t)b * CCH + c) * NTOK + t0 + tx] = tile[tx][ty + r * 8];
    }
}

// ---------------- packed-bf16 NT tensor-core GEMM ----------------
// C = alpha * A @ B^T + bias.
// A: [M][K2] packed uints (bf16 pairs along k). B: [N][K2] packed uints.
// Cb != 0 -> packed bf16 out (row length N/2 uints); else fp32 out to Cf.
// CTA 128x128, 256 threads (8 warps), warp tile 64x32, BK = 32 elems = 16 uints.
// SEG=24 swizzle: conflict-free fragment LDS.64. 2 CTAs/SM = 16 warps/SM.
__global__ void __launch_bounds__(256, 2)
hg_nt(const unsigned* __restrict__ A, const unsigned* __restrict__ B,
      unsigned* __restrict__ Cb, float* __restrict__ Cf,
      const float* __restrict__ bias,
      int N, int K2, float alpha, size_t sA, size_t sB, size_t sC) {
    A += (size_t)blockIdx.z * sA;
    B += (size_t)blockIdx.z * sB;

    __shared__ __align__(16) unsigned As[2][128 * SEG];
    __shared__ __align__(16) unsigned Bs[2][128 * SEG];

    const int tid  = threadIdx.x;
    const int lane = tid & 31;
    const int wid  = tid >> 5;          // 0..7
    const int wm   = (wid & 1) * 64;
    const int wn   = (wid >> 1) * 32;
    const int bm   = blockIdx.y * 128;
    const int bn   = blockIdx.x * 128;

    const int lrow = tid >> 1;          // 0..127: tile row this thread loads
    const int lhalf = tid & 1;          // 0/1: which 8-uint half of the row
    const unsigned* Ag = A + (size_t)(bm + lrow) * K2 + lhalf * 8;
    const unsigned* Bg = B + (size_t)(bn + lrow) * K2 + lhalf * 8;
    const int soff = lrow * SEG + lhalf * 8;

    const int g = lane >> 2;
    const int t = lane & 3;
    const int col0 = 2 * t;
    const int col1 = 8 + 2 * t;

    float acc[4][4][4];
#pragma unroll
    for (int i = 0; i < 4; i++)
#pragma unroll
        for (int j = 0; j < 4; j++)
#pragma unroll
            for (int u = 0; u < 4; u++) acc[i][j][u] = 0.f;

    const int nchunk = K2 / 16;
    uint4 ga[2], gb[2];

    // ---- prologue: load + store chunk 0 ----
    ga[0] = *(const uint4*)(Ag + 0);
    ga[1] = *(const uint4*)(Ag + 4);
    gb[0] = *(const uint4*)(Bg + 0);
    gb[1] = *(const uint4*)(Bg + 4);
    {
        unsigned* d = &As[0][soff];
        *(uint4*)(d + 0) = make_uint4(ga[0].x, ga[1].x, ga[0].y, ga[1].y);
        *(uint4*)(d + 4) = make_uint4(ga[0].z, ga[1].z, ga[0].w, ga[1].w);
        unsigned* e = &Bs[0][soff];
        *(uint4*)(e + 0) = make_uint4(gb[0].x, gb[1].x, gb[0].y, gb[1].y);
        *(uint4*)(e + 4) = make_uint4(gb[0].z, gb[1].z, gb[0].w, gb[1].w);
    }
    __syncthreads();

    for (int ch = 0; ch < nchunk; ch++) {
        const int st = ch & 1;
        if (ch + 1 < nchunk) {
            const int kc = (ch + 1) * 16;
            ga[0] = *(const uint4*)(Ag + kc + 0);
            ga[1] = *(const uint4*)(Ag + kc + 4);
            gb[0] = *(const uint4*)(Bg + kc + 0);
            gb[1] = *(const uint4*)(Bg + kc + 4);
        }

#pragma unroll
        for (int kk = 0; kk < 2; kk++) {
            const int cc = (kk == 0) ? col0 : col1;
            unsigned af[4][4];
#pragma unroll
            for (int mi = 0; mi < 4; mi++) {
                int r0 = wm + mi * 16 + g;
                uint2 u0 = *(const uint2*)&As[st][r0 * SEG + cc];
                uint2 u1 = *(const uint2*)&As[st][(r0 + 8) * SEG + cc];
                af[mi][0] = u0.x; af[mi][1] = u1.x;
                af[mi][2] = u0.y; af[mi][3] = u1.y;
            }
            unsigned bfr[4][2];
#pragma unroll
            for (int nj = 0; nj < 4; nj++) {
                int rb0 = wn + nj * 8 + g;
                uint2 ub = *(const uint2*)&Bs[st][rb0 * SEG + cc];
                bfr[nj][0] = ub.x; bfr[nj][1] = ub.y;
            }
#pragma unroll
            for (int mi = 0; mi < 4; mi++)
#pragma unroll
                for (int nj = 0; nj < 4; nj++)
                    mma16816(acc[mi][nj], af[mi], bfr[nj]);
        }

        if (ch + 1 < nchunk) {
            unsigned* d = &As[st ^ 1][soff];
            *(uint4*)(d + 0) = make_uint4(ga[0].x, ga[1].x, ga[0].y, ga[1].y);
            *(uint4*)(d + 4) = make_uint4(ga[0].z, ga[1].z, ga[0].w, ga[1].w);
            unsigned* e = &Bs[st ^ 1][soff];
            *(uint4*)(e + 0) = make_uint4(gb[0].x, gb[1].x, gb[0].y, gb[1].y);
            *(uint4*)(e + 4) = make_uint4(gb[0].z, gb[1].z, gb[0].w, gb[1].w);
        }
        __syncthreads();
    }

    // ---- epilogue ----
    const int lr  = g;
    const int lc2 = t * 2;
#pragma unroll
    for (int mi = 0; mi < 4; mi++) {
        int row0 = bm + wm + mi * 16 + lr;
#pragma unroll
        for (int nj = 0; nj < 4; nj++) {
            int col = bn + wn + nj * 8 + lc2;
            float b0 = 0.f, b1 = 0.f;
            if (bias) { b0 = bias[col]; b1 = bias[col + 1]; }
            float v0 = acc[mi][nj][0] * alpha + b0;
            float v1 = acc[mi][nj][1] * alpha + b1;
            float v2 = acc[mi][nj][2] * alpha + b0;
            float v3 = acc[mi][nj][3] * alpha + b1;
            if (Cb) {
                unsigned* C = Cb + blockIdx.z * sC;
                int n2 = N >> 1;
                C[(size_t)row0 * n2 + (col >> 1)]       = pack2(v0, v1);
                C[(size_t)(row0 + 8) * n2 + (col >> 1)] = pack2(v2, v3);
            } else {
                float* C = Cf + blockIdx.z * sC;
                *(float2*)(C + (size_t)row0 * N + col)       = make_float2(v0, v1);
                *(float2*)(C + (size_t)(row0 + 8) * N + col) = make_float2(v2, v3);
            }
        }
    }
}

// ---------------- row softmax: bf16 scores -> bf16 probs, in place ----------------
__global__ void softmax_rows_kernel() {
    size_t row = blockIdx.x;
    uint2* pr = (uint2*)(g_s32 + row * (size_t)(NTOK / 2));
    int t = threadIdx.x;
    float v[16];
    float lmax = -1e30f;
#pragma unroll
    for (int i = 0; i < 4; i++) {
        uint2 u = pr[t + i * 256];
        v[i * 4 + 0] = blo(u.x); v[i * 4 + 1] = bhi(u.x);
        v[i * 4 + 2] = blo(u.y); v[i * 4 + 3] = bhi(u.y);
        lmax = fmaxf(fmaxf(fmaxf(v[i * 4 + 0], v[i * 4 + 1]),
                           fmaxf(v[i * 4 + 2], v[i * 4 + 3])), lmax);
    }
    __shared__ float red[256];
    red[t] = lmax;
    __syncthreads();
    for (int o = 128; o > 0; o >>= 1) {
        if (t < o) red[t] = fmaxf(red[t], red[t + o]);
        __syncthreads();
    }
    float m = red[0];
    __syncthreads();
    float lsum = 0.f;
#pragma unroll
    for (int i = 0; i < 16; i++) {
        v[i] = __expf(v[i] - m);
        lsum += v[i];
    }
    red[t] = lsum;
    __syncthreads();
    for (int o = 128; o > 0; o >>= 1) {
        if (t < o) red[t] += red[t + o];
        __syncthreads();
    }
    float inv = 1.f / red[0];
#pragma unroll
    for (int i = 0; i < 4; i++) {
        uint2 w;
        w.x = pack2(v[i * 4 + 0] * inv, v[i * 4 + 1] * inv);
        w.y = pack2(v[i * 4 + 2] * inv, v[i * 4 + 3] * inv);
        pr[t + i * 256] = w;
    }
}

// ---------------- y[b,s,c] -> out[b,c,s] + residual ----------------
__global__ void add_residual_transpose_kernel(const float* __restrict__ x,
                                              float* __restrict__ out) {
    __shared__ float tile[32][33];
    int b  = blockIdx.z;
    int c0 = blockIdx.y * 32;
    int s0 = blockIdx.x * 32;
    int tx = threadIdx.x, ty = threadIdx.y;
#pragma unroll
    for (int r = 0; r < 4; r++) {
        int s = s0 + ty + r * 8;
        tile[ty + r * 8][tx] = g_y[((size_t)b * NTOK + s) * CCH + c0 + tx];
    }
    __syncthreads();
#pragma unroll
    for (int r = 0; r < 4; r++) {
        int c = c0 + ty + r * 8;
        size_t idx = ((size_t)b * CCH + c) * HW + s0 + tx;
        out[idx] = tile[tx][ty + r * 8] + x[idx];
    }
}

// ---------------- launch ----------------
extern "C" void kernel_launch(void* const* d_in, const int* in_sizes, int n_in,
                              void* d_out, int out_size) {
    const float* x     = (const float*)d_in[0];
    const float* gamma = (const float*)d_in[1];
    const float* beta  = (const float*)d_in[2];
    const float* wq_w  = (const float*)d_in[3];
    const float* wq_b  = (const float*)d_in[4];
    const float* wk_w  = (const float*)d_in[5];
    const float* wk_b  = (const float*)d_in[6];
    const float* wv_w  = (const float*)d_in[7];
    const float* wv_b  = (const float*)d_in[8];
    const float* out_w = (const float*)d_in[9];
    const float* out_b = (const float*)d_in[10];
    float* out = (float*)d_out;

    unsigned *tbuf, *qbuf, *kbuf, *vbuf, *vtbuf, *obuf, *wbuf, *sbuf;
    float *ybuf;
    cudaGetSymbolAddress((void**)&tbuf,  g_t32);
    cudaGetSymbolAddress((void**)&qbuf,  g_q32);
    cudaGetSymbolAddress((void**)&kbuf,  g_k32);
    cudaGetSymbolAddress((void**)&vbuf,  g_v32);
    cudaGetSymbolAddress((void**)&vtbuf, g_vt32);
    cudaGetSymbolAddress((void**)&obuf,  g_o32);
    cudaGetSymbolAddress((void**)&wbuf,  g_w32);
    cudaGetSymbolAddress((void**)&sbuf,  g_s32);
    cudaGetSymbolAddress((void**)&ybuf,  g_y);

    const int WU = CCH * CCH / 2;                  // uints per weight matrix
    const int MT = BATCH * NTOK;                   // 16384 rows
    const int K2C = CCH / 2;                       // 256 uints
    const int K2T = NTOK / 2;                      // 2048 uints
    dim3 tthr(32, 8);

    gn_stats_kernel<<<BATCH * NGROUPS, 256>>>(x);
    gn_apply_transpose_kernel<<<dim3(HW / 32, CCH / 32, BATCH), tthr>>>(x, gamma, beta);
    conv_w_kernel<<<CCH * CCH / 1024, 256>>>(wq_w, wbuf + 0 * WU);
    conv_w_kernel<<<CCH * CCH / 1024, 256>>>(wk_w, wbuf + 1 * WU);
    conv_w_kernel<<<CCH * CCH / 1024, 256>>>(wv_w, wbuf + 2 * WU);
    conv_w_kernel<<<CCH * CCH / 1024, 256>>>(out_w, wbuf + 3 * WU);

    // Q/K/V projections (NT, bias fused, packed-bf16 out)
    hg_nt<<<dim3(CCH / 128, MT / 128, 1), 256>>>(
        tbuf, wbuf + 0 * WU, qbuf, 0, wq_b, CCH, K2C, 1.f, 0, 0, 0);
    hg_nt<<<dim3(CCH / 128, MT / 128, 1), 256>>>(
        tbuf, wbuf + 1 * WU, kbuf, 0, wk_b, CCH, K2C, 1.f, 0, 0, 0);
    hg_nt<<<dim3(CCH / 128, MT / 128, 1), 256>>>(
        tbuf, wbuf + 2 * WU, vbuf, 0, wv_b, CCH, K2C, 1.f, 0, 0, 0);

    // V transpose: v[b][tok][c] -> vt[b][c][tok]
    transpose_v_kernel<<<dim3(NTOK / 32, CCH / 32, BATCH), tthr>>>();

    // scores = Q @ K^T * scale (batched NT, packed-bf16 out)
    hg_nt<<<dim3(NTOK / 128, NTOK / 128, BATCH), 256>>>(
        qbuf, kbuf, sbuf, 0, 0, NTOK, K2C, SCALE_QK,
        (size_t)NTOK * K2C, (size_t)NTOK * K2C, (size_t)NTOK * NTOK / 2);

    // softmax in place: bf16 scores -> bf16 probs
    softmax_rows_kernel<<<BATCH * NTOK, 256>>>();

    // O = P @ V = P @ (VT)^T (batched NT, packed-bf16 out)
    hg_nt<<<dim3(CCH / 128, NTOK / 128, BATCH), 256>>>(
        sbuf, vtbuf, obuf, 0, 0, CCH, K2T, 1.f,
        (size_t)NTOK * K2T, (size_t)CCH * K2T, (size_t)NTOK * K2C);

    // out projection (NT, bias fused, fp32 out)
    hg_nt<<<dim3(CCH / 128, MT / 128, 1), 256>>>(
        obuf, wbuf + 3 * WU, 0, ybuf, out_b, CCH, K2C, 1.f, 0, 0, 0);

    add_residual_transpose_kernel<<<dim3(HW / 32, CCH / 32, BATCH), tthr>>>(x, out);
}

// round 15
// speedup vs baseline: 2.7376x; 1.0188x over previous
#include <cuda_runtime.h>
#include <math.h>

#define BATCH 4
#define CCH   512
#define HW    4096
#define NTOK  4096
#define NGROUPS 32
#define CPG   16
#define GSIZE (CPG * HW)
#define SCALE_QK 0.044194173824159216f
#define SEG   24

// ---------------- scratch (packed bf16x2 stored as unsigned) ----------------
__device__ unsigned g_t32[BATCH * NTOK * CCH / 2];
__device__ unsigned g_qkv32[BATCH * NTOK * 3 * CCH / 2];      // [row][768]: Q|K|V packed
__device__ unsigned g_vt32[BATCH * NTOK * CCH / 2];
__device__ unsigned g_o32[BATCH * NTOK * CCH / 2];
__device__ unsigned g_w32[4 * CCH * CCH / 2];
__device__ float    g_bqkv[3 * CCH];
__device__ float    g_y[BATCH * NTOK * CCH];
__device__ unsigned g_s32[(size_t)BATCH * NTOK * NTOK / 2];   // bf16 scores -> probs (in place)
__device__ float    g_stats[BATCH * NGROUPS * 2];

// ---------------- helpers ----------------
__device__ __forceinline__ unsigned pack2(float lo, float hi) {
    unsigned r;
    asm("cvt.rn.bf16x2.f32 %0, %1, %2;" : "=r"(r) : "f"(hi), "f"(lo));
    return r;
}
__device__ __forceinline__ float blo(unsigned u) { return __uint_as_float(u << 16); }
__device__ __forceinline__ float bhi(unsigned u) { return __uint_as_float(u & 0xffff0000u); }
__device__ __forceinline__ void mma16816(float* c, const unsigned* a, const unsigned* b) {
    asm volatile(
        "mma.sync.aligned.m16n8k16.row.col.f32.bf16.bf16.f32 "
        "{%0,%1,%2,%3}, {%4,%5,%6,%7}, {%8,%9}, {%0,%1,%2,%3};"
        : "+f"(c[0]), "+f"(c[1]), "+f"(c[2]), "+f"(c[3])
        : "r"(a[0]), "r"(a[1]), "r"(a[2]), "r"(a[3]), "r"(b[0]), "r"(b[1]));
}

// ---------------- GroupNorm stats ----------------
__global__ void gn_stats_kernel(const float* __restrict__ x) {
    int bg = blockIdx.x;
    const float4* p = (const float4*)(x + (size_t)bg * GSIZE);
    float s = 0.f, sq = 0.f;
    for (int i = threadIdx.x; i < GSIZE / 4; i += blockDim.x) {
        float4 v = p[i];
        s  += v.x + v.y + v.z + v.w;
        sq += v.x * v.x + v.y * v.y + v.z * v.z + v.w * v.w;
    }
    __shared__ float rs[256];
    __shared__ float rq[256];
    rs[threadIdx.x] = s; rq[threadIdx.x] = sq;
    __syncthreads();
    for (int o = 128; o > 0; o >>= 1) {
        if (threadIdx.x < o) {
            rs[threadIdx.x] += rs[threadIdx.x + o];
            rq[threadIdx.x] += rq[threadIdx.x + o];
        }
        __syncthreads();
    }
    if (threadIdx.x == 0) {
        float mean = rs[0] / (float)GSIZE;
        float var  = rq[0] / (float)GSIZE - mean * mean;
        g_stats[bg * 2 + 0] = mean;
        g_stats[bg * 2 + 1] = rsqrtf(var + 1e-6f);
    }
}

// ---------------- normalize + affine + transpose -> packed bf16 token-major ----------------
__global__ void gn_apply_transpose_kernel(const float* __restrict__ x,
                                          const float* __restrict__ gamma,
                                          const float* __restrict__ beta) {
    __shared__ float tile[32][33];
    int b  = blockIdx.z;
    int c0 = blockIdx.y * 32;
    int s0 = blockIdx.x * 32;
    int tx = threadIdx.x, ty = threadIdx.y;
#pragma unroll
    for (int r = 0; r < 4; r++) {
        int c = c0 + ty + r * 8;
        int g = c / CPG;
        float mean = g_stats[(b * NGROUPS + g) * 2 + 0];
        float rstd = g_stats[(b * NGROUPS + g) * 2 + 1];
        float v = x[((size_t)b * CCH + c) * HW + s0 + tx];
        tile[ty + r * 8][tx] = (v - mean) * rstd * gamma[c] + beta[c];
    }
    __syncthreads();
    if (tx < 16) {
#pragma unroll
        for (int r = 0; r < 4; r++) {
            int sl = ty + r * 8;
            float lo = tile[2 * tx + 0][sl];
            float hi = tile[2 * tx + 1][sl];
            g_t32[((size_t)b * NTOK + s0 + sl) * (CCH / 2) + (c0 >> 1) + tx] = pack2(lo, hi);
        }
    }
}

// ---------------- fp32 -> packed bf16 weight convert ----------------
__global__ void conv_w_kernel(const float* __restrict__ w, unsigned* __restrict__ o) {
    int i = blockIdx.x * 256 + threadIdx.x;
    float4 v = ((const float4*)w)[i];
    o[2 * i + 0] = pack2(v.x, v.y);
    o[2 * i + 1] = pack2(v.z, v.w);
}

// ---------------- concat Q/K/V biases into g_bqkv[1536] ----------------
__global__ void concat_bias_kernel(const float* __restrict__ bq,
                                   const float* __restrict__ bk,
                                   const float* __restrict__ bv) {
    int i = blockIdx.x * 256 + threadIdx.x;   // 0..1535
    float v;
    if (i < CCH) v = bq[i];
    else if (i < 2 * CCH) v = bk[i - CCH];
    else v = bv[i - 2 * CCH];
    g_bqkv[i] = v;
}

// ---------------- bf16 transpose: qkv V block [b,tok,c] -> vt[b,c,tok] ----------------
__global__ void transpose_v_kernel() {
    __shared__ unsigned short tile[32][33];
    const unsigned short* in = (const unsigned short*)g_qkv32;
    unsigned short* out = (unsigned short*)g_vt32;
    int b  = blockIdx.z;
    int t0 = blockIdx.x * 32;
    int c0 = blockIdx.y * 32;
    int tx = threadIdx.x, ty = threadIdx.y;
#pragma unroll
    for (int r = 0; r < 4; r++) {
        int tk = t0 + ty + r * 8;
        tile[ty + r * 8][tx] = in[((size_t)b * NTOK + tk) * (3 * CCH) + 2 * CCH + c0 + tx];
    }
    __syncthreads();
#pragma unroll
    for (int r = 0; r < 4; r++) {
        int c = c0 + ty + r * 8;
        out[((size_t)b * CCH + c) * NTOK + t0 + tx] = tile[tx][ty + r * 8];
    }
}

// ---------------- packed-bf16 NT tensor-core GEMM ----------------
// C = alpha * A @ B^T + bias.
// A rows at stride ldA uints (K2 uints used). B rows at stride ldB uints.
// Cb != 0 -> packed bf16 out (row stride N/2 uints); else fp32 out to Cf.
// CTA 128x128, 256 threads (8 warps), warp tile 64x32, BK = 32 elems = 16 uints.
// SEG=24 swizzle: conflict-free fragment LDS.64. 2 CTAs/SM = 16 warps/SM.
__global__ void __launch_bounds__(256, 2)
hg_nt(const unsigned* __restrict__ A, const unsigned* __restrict__ B,
      unsigned* __restrict__ Cb, float* __restrict__ Cf,
      const float* __restrict__ bias,
      int N, int K2, int ldA, int ldB, float alpha,
      size_t sA, size_t sB, size_t sC) {
    A += (size_t)blockIdx.z * sA;
    B += (size_t)blockIdx.z * sB;

    __shared__ __align__(16) unsigned As[2][128 * SEG];
    __shared__ __align__(16) unsigned Bs[2][128 * SEG];

    const int tid  = threadIdx.x;
    const int lane = tid & 31;
    const int wid  = tid >> 5;          // 0..7
    const int wm   = (wid & 1) * 64;
    const int wn   = (wid >> 1) * 32;
    const int bm   = blockIdx.y * 128;
    const int bn   = blockIdx.x * 128;

    const int lrow = tid >> 1;          // 0..127: tile row this thread loads
    const int lhalf = tid & 1;          // 0/1: which 8-uint half of the row
    const unsigned* Ag = A + (size_t)(bm + lrow) * ldA + lhalf * 8;
    const unsigned* Bg = B + (size_t)(bn + lrow) * ldB + lhalf * 8;
    const int soff = lrow * SEG + lhalf * 8;

    const int g = lane >> 2;
    const int t = lane & 3;
    const int col0 = 2 * t;
    const int col1 = 8 + 2 * t;

    float acc[4][4][4];
#pragma unroll
    for (int i = 0; i < 4; i++)
#pragma unroll
        for (int j = 0; j < 4; j++)
#pragma unroll
            for (int u = 0; u < 4; u++) acc[i][j][u] = 0.f;

    const int nchunk = K2 / 16;
    uint4 ga[2], gb[2];

    // ---- prologue: load + store chunk 0 ----
    ga[0] = *(const uint4*)(Ag + 0);
    ga[1] = *(const uint4*)(Ag + 4);
    gb[0] = *(const uint4*)(Bg + 0);
    gb[1] = *(const uint4*)(Bg + 4);
    {
        unsigned* d = &As[0][soff];
        *(uint4*)(d + 0) = make_uint4(ga[0].x, ga[1].x, ga[0].y, ga[1].y);
        *(uint4*)(d + 4) = make_uint4(ga[0].z, ga[1].z, ga[0].w, ga[1].w);
        unsigned* e = &Bs[0][soff];
        *(uint4*)(e + 0) = make_uint4(gb[0].x, gb[1].x, gb[0].y, gb[1].y);
        *(uint4*)(e + 4) = make_uint4(gb[0].z, gb[1].z, gb[0].w, gb[1].w);
    }
    __syncthreads();

    for (int ch = 0; ch < nchunk; ch++) {
        const int st = ch & 1;
        if (ch + 1 < nchunk) {
            const int kc = (ch + 1) * 16;
            ga[0] = *(const uint4*)(Ag + kc + 0);
            ga[1] = *(const uint4*)(Ag + kc + 4);
            gb[0] = *(const uint4*)(Bg + kc + 0);
            gb[1] = *(const uint4*)(Bg + kc + 4);
        }

#pragma unroll
        for (int kk = 0; kk < 2; kk++) {
            const int cc = (kk == 0) ? col0 : col1;
            unsigned af[4][4];
#pragma unroll
            for (int mi = 0; mi < 4; mi++) {
                int r0 = wm + mi * 16 + g;
                uint2 u0 = *(const uint2*)&As[st][r0 * SEG + cc];
                uint2 u1 = *(const uint2*)&As[st][(r0 + 8) * SEG + cc];
                af[mi][0] = u0.x; af[mi][1] = u1.x;
                af[mi][2] = u0.y; af[mi][3] = u1.y;
            }
            unsigned bfr[4][2];
#pragma unroll
            for (int nj = 0; nj < 4; nj++) {
                int rb0 = wn + nj * 8 + g;
                uint2 ub = *(const uint2*)&Bs[st][rb0 * SEG + cc];
                bfr[nj][0] = ub.x; bfr[nj][1] = ub.y;
            }
#pragma unroll
            for (int mi = 0; mi < 4; mi++)
#pragma unroll
                for (int nj = 0; nj < 4; nj++)
                    mma16816(acc[mi][nj], af[mi], bfr[nj]);
        }

        if (ch + 1 < nchunk) {
            unsigned* d = &As[st ^ 1][soff];
            *(uint4*)(d + 0) = make_uint4(ga[0].x, ga[1].x, ga[0].y, ga[1].y);
            *(uint4*)(d + 4) = make_uint4(ga[0].z, ga[1].z, ga[0].w, ga[1].w);
            unsigned* e = &Bs[st ^ 1][soff];
            *(uint4*)(e + 0) = make_uint4(gb[0].x, gb[1].x, gb[0].y, gb[1].y);
            *(uint4*)(e + 4) = make_uint4(gb[0].z, gb[1].z, gb[0].w, gb[1].w);
        }
        __syncthreads();
    }

    // ---- epilogue ----
    const int lr  = g;
    const int lc2 = t * 2;
#pragma unroll
    for (int mi = 0; mi < 4; mi++) {
        int row0 = bm + wm + mi * 16 + lr;
#pragma unroll
        for (int nj = 0; nj < 4; nj++) {
            int col = bn + wn + nj * 8 + lc2;
            float b0 = 0.f, b1 = 0.f;
            if (bias) { b0 = bias[col]; b1 = bias[col + 1]; }
            float v0 = acc[mi][nj][0] * alpha + b0;
            float v1 = acc[mi][nj][1] * alpha + b1;
            float v2 = acc[mi][nj][2] * alpha + b0;
            float v3 = acc[mi][nj][3] * alpha + b1;
            if (Cb) {
                unsigned* C = Cb + blockIdx.z * sC;
                int n2 = N >> 1;
                C[(size_t)row0 * n2 + (col >> 1)]       = pack2(v0, v1);
                C[(size_t)(row0 + 8) * n2 + (col >> 1)] = pack2(v2, v3);
            } else {
                float* C = Cf + blockIdx.z * sC;
                *(float2*)(C + (size_t)row0 * N + col)       = make_float2(v0, v1);
                *(float2*)(C + (size_t)(row0 + 8) * N + col) = make_float2(v2, v3);
            }
        }
    }
}

// ---------------- row softmax: bf16 scores -> bf16 probs, in place ----------------
__global__ void softmax_rows_kernel() {
    size_t row = blockIdx.x;
    uint2* pr = (uint2*)(g_s32 + row * (size_t)(NTOK / 2));
    int t = threadIdx.x;
    float v[16];
    float lmax = -1e30f;
#pragma unroll
    for (int i = 0; i < 4; i++) {
        uint2 u = pr[t + i * 256];
        v[i * 4 + 0] = blo(u.x); v[i * 4 + 1] = bhi(u.x);
        v[i * 4 + 2] = blo(u.y); v[i * 4 + 3] = bhi(u.y);
        lmax = fmaxf(fmaxf(fmaxf(v[i * 4 + 0], v[i * 4 + 1]),
                           fmaxf(v[i * 4 + 2], v[i * 4 + 3])), lmax);
    }
    __shared__ float red[256];
    red[t] = lmax;
    __syncthreads();
    for (int o = 128; o > 0; o >>= 1) {
        if (t < o) red[t] = fmaxf(red[t], red[t + o]);
        __syncthreads();
    }
    float m = red[0];
    __syncthreads();
    float lsum = 0.f;
#pragma unroll
    for (int i = 0; i < 16; i++) {
        v[i] = __expf(v[i] - m);
        lsum += v[i];
    }
    red[t] = lsum;
    __syncthreads();
    for (int o = 128; o > 0; o >>= 1) {
        if (t < o) red[t] += red[t + o];
        __syncthreads();
    }
    float inv = 1.f / red[0];
#pragma unroll
    for (int i = 0; i < 4; i++) {
        uint2 w;
        w.x = pack2(v[i * 4 + 0] * inv, v[i * 4 + 1] * inv);
        w.y = pack2(v[i * 4 + 2] * inv, v[i * 4 + 3] * inv);
        pr[t + i * 256] = w;
    }
}

// ---------------- y[b,s,c] -> out[b,c,s] + residual ----------------
__global__ void add_residual_transpose_kernel(const float* __restrict__ x,
                                              float* __restrict__ out) {
    __shared__ float tile[32][33];
    int b  = blockIdx.z;
    int c0 = blockIdx.y * 32;
    int s0 = blockIdx.x * 32;
    int tx = threadIdx.x, ty = threadIdx.y;
#pragma unroll
    for (int r = 0; r < 4; r++) {
        int s = s0 + ty + r * 8;
        tile[ty + r * 8][tx] = g_y[((size_t)b * NTOK + s) * CCH + c0 + tx];
    }
    __syncthreads();
#pragma unroll
    for (int r = 0; r < 4; r++) {
        int c = c0 + ty + r * 8;
        size_t idx = ((size_t)b * CCH + c) * HW + s0 + tx;
        out[idx] = tile[tx][ty + r * 8] + x[idx];
    }
}

// ---------------- launch ----------------
extern "C" void kernel_launch(void* const* d_in, const int* in_sizes, int n_in,
                              void* d_out, int out_size) {
    const float* x     = (const float*)d_in[0];
    const float* gamma = (const float*)d_in[1];
    const float* beta  = (const float*)d_in[2];
    const float* wq_w  = (const float*)d_in[3];
    const float* wq_b  = (const float*)d_in[4];
    const float* wk_w  = (const float*)d_in[5];
    const float* wk_b  = (const float*)d_in[6];
    const float* wv_w  = (const float*)d_in[7];
    const float* wv_b  = (const float*)d_in[8];
    const float* out_w = (const float*)d_in[9];
    const float* out_b = (const float*)d_in[10];
    float* out = (float*)d_out;

    unsigned *tbuf, *qkvbuf, *vtbuf, *obuf, *wbuf, *sbuf;
    float *ybuf, *bqkv;
    cudaGetSymbolAddress((void**)&tbuf,   g_t32);
    cudaGetSymbolAddress((void**)&qkvbuf, g_qkv32);
    cudaGetSymbolAddress((void**)&vtbuf,  g_vt32);
    cudaGetSymbolAddress((void**)&obuf,   g_o32);
    cudaGetSymbolAddress((void**)&wbuf,   g_w32);
    cudaGetSymbolAddress((void**)&sbuf,   g_s32);
    cudaGetSymbolAddress((void**)&ybuf,   g_y);
    cudaGetSymbolAddress((void**)&bqkv,   g_bqkv);

    const int WU  = CCH * CCH / 2;   // uints per weight matrix
    const int MT  = BATCH * NTOK;    // 16384 rows
    const int K2C = CCH / 2;         // 256 uints
    const int K2T = NTOK / 2;        // 2048 uints
    const int LDQ = 3 * CCH / 2;     // 768 uints: qkv row stride
    dim3 tthr(32, 8);

    gn_stats_kernel<<<BATCH * NGROUPS, 256>>>(x);
    gn_apply_transpose_kernel<<<dim3(HW / 32, CCH / 32, BATCH), tthr>>>(x, gamma, beta);
    conv_w_kernel<<<CCH * CCH / 1024, 256>>>(wq_w, wbuf + 0 * WU);
    conv_w_kernel<<<CCH * CCH / 1024, 256>>>(wk_w, wbuf + 1 * WU);
    conv_w_kernel<<<CCH * CCH / 1024, 256>>>(wv_w, wbuf + 2 * WU);
    conv_w_kernel<<<CCH * CCH / 1024, 256>>>(out_w, wbuf + 3 * WU);
    concat_bias_kernel<<<3 * CCH / 256, 256>>>(wq_b, wk_b, wv_b);

    // fused Q|K|V projection: [MT,512] @ [1536,512]^T -> qkv[MT][1536] bf16
    hg_nt<<<dim3(3 * CCH / 128, MT / 128, 1), 256>>>(
        tbuf, wbuf, qkvbuf, 0, bqkv, 3 * CCH, K2C, K2C, K2C, 1.f, 0, 0, 0);

    // V transpose: qkv V block -> vt[b][c][tok]
    transpose_v_kernel<<<dim3(NTOK / 32, CCH / 32, BATCH), tthr>>>();

    // scores = Q @ K^T * scale (packed-bf16 out)
    hg_nt<<<dim3(NTOK / 128, NTOK / 128, BATCH), 256>>>(
        qkvbuf, qkvbuf + K2C, sbuf, 0, 0, NTOK, K2C, LDQ, LDQ, SCALE_QK,
        (size_t)NTOK * LDQ, (size_t)NTOK * LDQ, (size_t)NTOK * NTOK / 2);

    // softmax in place: bf16 scores -> bf16 probs
    softmax_rows_kernel<<<BATCH * NTOK, 256>>>();

    // O = P @ V = P @ (VT)^T (packed-bf16 out)
    hg_nt<<<dim3(CCH / 128, NTOK / 128, BATCH), 256>>>(
        sbuf, vtbuf, obuf, 0, 0, CCH, K2T, K2T, K2T, 1.f,
        (size_t)NTOK * K2T, (size_t)CCH * K2T, (size_t)NTOK * K2C);

    // out projection (bias fused, fp32 out)
    hg_nt<<<dim3(CCH / 128, MT / 128, 1), 256>>>(
        obuf, wbuf + 3 * WU, 0, ybuf, out_b, CCH, K2C, K2C, K2C, 1.f, 0, 0, 0);

    add_residual_transpose_kernel<<<dim3(HW / 32, CCH / 32, BATCH), tthr>>>(x, out);
}